// round 15
// baseline (speedup 1.0000x reference)
#include <cuda_runtime.h>
#include <cuda_bf16.h>
#include <cstdint>

// ESN collapsed op: out[bt, r] = (1 - lr) * tanh( sum_i x[bt,i] * w[r,i] )
// B*T = 1,048,576 rows, I = 8, R = 128. Store-stream bound (~537MB out).
// R13: FULL-ROW warp mapping (lane owns r = 4*lane..4*lane+3, one STG.128)
// on the champion 4-stage cp.async ring (TILE=128, 3-tile lead, 1 barrier).
// ~25% fewer issue slots per row than the half-row champion.

__device__ __forceinline__ unsigned long long pk2(float lo, float hi) {
    unsigned long long r;
    asm("mov.b64 %0, {%1, %2};" : "=l"(r) : "f"(lo), "f"(hi));
    return r;
}
__device__ __forceinline__ void upk2(float& lo, float& hi, unsigned long long v) {
    asm("mov.b64 {%0, %1}, %2;" : "=f"(lo), "=f"(hi) : "l"(v));
}
__device__ __forceinline__ unsigned long long mul2(unsigned long long a, unsigned long long b) {
    unsigned long long r;
    asm("mul.rn.f32x2 %0, %1, %2;" : "=l"(r) : "l"(a), "l"(b));
    return r;
}
__device__ __forceinline__ unsigned long long fma2(unsigned long long a, unsigned long long b,
                                                   unsigned long long c) {
    unsigned long long r;
    asm("fma.rn.f32x2 %0, %1, %2, %3;" : "=l"(r) : "l"(a), "l"(b), "l"(c));
    return r;
}
__device__ __forceinline__ float tanh_ap(float x) {
    float y;
    asm("tanh.approx.f32 %0, %1;" : "=f"(y) : "f"(x));
    return y;
}

static constexpr int TILE = 128;           // rows per stage per block
static constexpr int TILE_F = TILE * 8;    // floats per stage (1024 = 4KB)
static constexpr int STAGES = 4;           // ring depth (16KB total)

__global__ void __launch_bounds__(256, 4) ESN_11390253269642_kernel(
    const float* __restrict__ x,     // [BT, 8]
    const float* __restrict__ w,     // [128, 8]
    const float* __restrict__ lrp,   // [1]
    float* __restrict__ out,         // [BT, 128]
    int bt_total)
{
    __shared__ float xs[STAGES][TILE_F];

    const int tid  = threadIdx.x;
    const int lane = tid & 31;
    const int wid  = tid >> 5;           // 0..7 ; warp handles rows wid, wid+8, ...
    const float s = 1.0f - __ldg(lrp);

    // Lane owns r = 4*lane + q, q = 0..3. 32 floats of w, packed f32x2.
    unsigned long long wq[4][4];
#pragma unroll
    for (int q = 0; q < 4; q++) {
        const float4* p = reinterpret_cast<const float4*>(w + (lane * 4 + q) * 8);
        float4 a = __ldg(p), b = __ldg(p + 1);
        wq[q][0] = pk2(a.x, a.y); wq[q][1] = pk2(a.z, a.w);
        wq[q][2] = pk2(b.x, b.y); wq[q][3] = pk2(b.z, b.w);
    }

    const long long total_f = (long long)bt_total * 8;
    const int ntiles = (bt_total + TILE - 1) / TILE;
    const int g = gridDim.x;

    // cp.async: 256 threads x 16B = 4KB = one full tile.
    auto issue_tile = [&](int tile, int buf) {
        if (tile < ntiles) {
            long long off = (long long)tile * TILE_F + tid * 4;
            if (off < total_f) {
                uint32_t dst = (uint32_t)__cvta_generic_to_shared(&xs[buf][tid * 4]);
                asm volatile("cp.async.ca.shared.global [%0], [%1], 16;"
                             :: "r"(dst), "l"(x + off));
            }
        }
    };

    issue_tile(blockIdx.x,         0);
    asm volatile("cp.async.commit_group;");
    issue_tile(blockIdx.x + g,     1);
    asm volatile("cp.async.commit_group;");
    issue_tile(blockIdx.x + 2 * g, 2);
    asm volatile("cp.async.commit_group;");

    int i = 0;
    for (int tile = blockIdx.x; tile < ntiles; tile += g, i++) {
        asm volatile("cp.async.wait_group 2;");
        __syncthreads();   // stage ready + all warps past last reads of reused stage

        const int buf = i & (STAGES - 1);
        const int rowlim = bt_total - tile * TILE;
        // warp handles rows wid + 8*j, j = 0..15
        uint32_t xaddr = (uint32_t)__cvta_generic_to_shared(&xs[buf][wid * 8]);
        float* obase = out + (size_t)(tile * TILE + wid) * 128 + lane * 4;
#pragma unroll 4
        for (int j = 0; j < 16; j++) {
            int rit = wid + j * 8;
            if (rit >= rowlim) break;
            unsigned long long xv0, xv1, xv2, xv3;
            uint32_t a = xaddr + (uint32_t)(j * 8 * 32);   // 8 rows * 32B per j-step
            asm volatile("ld.shared.v2.u64 {%0, %1}, [%2];"
                         : "=l"(xv0), "=l"(xv1) : "r"(a));
            asm volatile("ld.shared.v2.u64 {%0, %1}, [%2];"
                         : "=l"(xv2), "=l"(xv3) : "r"(a + 16));

            float4 o;
            float* op = &o.x;
#pragma unroll
            for (int q = 0; q < 4; q++) {
                unsigned long long acc = mul2(wq[q][0], xv0);
                acc = fma2(wq[q][1], xv1, acc);
                acc = fma2(wq[q][2], xv2, acc);
                acc = fma2(wq[q][3], xv3, acc);
                float lo, hi;
                upk2(lo, hi, acc);
                op[q] = s * tanh_ap(lo + hi);
            }
            __stcs(reinterpret_cast<float4*>(obase + (size_t)j * 8 * 128), o);
        }

        issue_tile(tile + 3 * g, (i + 3) & (STAGES - 1));
        asm volatile("cp.async.commit_group;");
    }
}

extern "C" void kernel_launch(void* const* d_in, const int* in_sizes, int n_in,
                              void* d_out, int out_size)
{
    const float* x   = (const float*)d_in[0];   // [B, T, I] fp32
    const float* w   = (const float*)d_in[1];   // [R, I] fp32
    // d_in[2] = d, unused (contributes exactly 0 in the reference)
    const float* lr  = (const float*)d_in[3];   // [1] fp32
    float* out = (float*)d_out;

    const int bt_total = in_sizes[0] / 8;       // B*T rows

    int ntiles = (bt_total + TILE - 1) / TILE;
    int blocks = 592;                            // 4 blocks/SM x 148 SMs
    if (blocks > ntiles) blocks = ntiles;
    if (blocks < 1) blocks = 1;
    ESN_11390253269642_kernel<<<blocks, 256>>>(x, w, lr, out, bt_total);
}

// round 17
// speedup vs baseline: 1.0688x; 1.0688x over previous
#include <cuda_runtime.h>
#include <cuda_bf16.h>
#include <cstdint>

// ESN collapsed op: out[bt, r] = (1 - lr) * tanh( sum_i x[bt,i] * w[r,i] )
// B*T = 1,048,576 rows, I = 8, R = 128. Store-stream bound (~537MB out).
// CHAMPION (R4, best measured 88.3us; plateau at ~5.2TB/s effective DRAM):
// cp.async double-buffered x staging (TILE=128), warp = half row,
// lane owns (r0, r0+1), predicated unroll-4 loop, 6 blocks/SM.

__device__ __forceinline__ unsigned long long pk2(float lo, float hi) {
    unsigned long long r;
    asm("mov.b64 %0, {%1, %2};" : "=l"(r) : "f"(lo), "f"(hi));
    return r;
}
__device__ __forceinline__ void upk2(float& lo, float& hi, unsigned long long v) {
    asm("mov.b64 {%0, %1}, %2;" : "=f"(lo), "=f"(hi) : "l"(v));
}
__device__ __forceinline__ unsigned long long mul2(unsigned long long a, unsigned long long b) {
    unsigned long long r;
    asm("mul.rn.f32x2 %0, %1, %2;" : "=l"(r) : "l"(a), "l"(b));
    return r;
}
__device__ __forceinline__ unsigned long long fma2(unsigned long long a, unsigned long long b,
                                                   unsigned long long c) {
    unsigned long long r;
    asm("fma.rn.f32x2 %0, %1, %2, %3;" : "=l"(r) : "l"(a), "l"(b), "l"(c));
    return r;
}
__device__ __forceinline__ float tanh_ap(float x) {
    float y;
    asm("tanh.approx.f32 %0, %1;" : "=f"(y) : "f"(x));
    return y;
}

static constexpr int TILE = 128;           // rows per stage per block
static constexpr int TILE_F = TILE * 8;    // floats per stage (1024 = 4KB)

__global__ void __launch_bounds__(256, 6) ESN_11390253269642_kernel(
    const float* __restrict__ x,     // [BT, 8]
    const float* __restrict__ w,     // [128, 8]
    const float* __restrict__ lrp,   // [1]
    float* __restrict__ out,         // [BT, 128]
    int bt_total)
{
    __shared__ float xs[2][TILE_F];

    const int tid  = threadIdx.x;
    const int lane = tid & 31;
    const int wid  = tid >> 5;           // 0..7
    const int half = wid & 1;            // which 64-wide half of the row
    const int wrow = wid >> 1;           // 0..3: row offset within stride-4 groups
    const float s = 1.0f - __ldg(lrp);

    // This lane owns r0 = half*64 + lane*2 and r1 = r0+1.
    // w rows packed as f32x2 pairs (one-time cost).
    unsigned long long w0[4], w1[4];
    {
        const int r0 = half * 64 + lane * 2;
        const float4* p0 = reinterpret_cast<const float4*>(w + r0 * 8);
        float4 a = __ldg(p0), b = __ldg(p0 + 1);
        w0[0] = pk2(a.x, a.y); w0[1] = pk2(a.z, a.w);
        w0[2] = pk2(b.x, b.y); w0[3] = pk2(b.z, b.w);
        const float4* p1 = reinterpret_cast<const float4*>(w + (r0 + 1) * 8);
        a = __ldg(p1); b = __ldg(p1 + 1);
        w1[0] = pk2(a.x, a.y); w1[1] = pk2(a.z, a.w);
        w1[2] = pk2(b.x, b.y); w1[3] = pk2(b.z, b.w);
    }

    const long long total_f = (long long)bt_total * 8;
    const int ntiles = (bt_total + TILE - 1) / TILE;

    // cp.async: 256 threads x 16B = 4KB = one full tile
    auto issue_tile = [&](int tile, int buf) {
        long long off = (long long)tile * TILE_F + tid * 4;
        if (off < total_f) {
            uint32_t dst = (uint32_t)__cvta_generic_to_shared(&xs[buf][tid * 4]);
            const float* src = x + off;
            asm volatile("cp.async.ca.shared.global [%0], [%1], 16;"
                         :: "r"(dst), "l"(src));
        }
    };

    int tile = blockIdx.x;
    int buf = 0;
    if (tile < ntiles) issue_tile(tile, 0);
    asm volatile("cp.async.commit_group;");

    for (; tile < ntiles; tile += gridDim.x) {
        int next = tile + gridDim.x;
        if (next < ntiles) issue_tile(next, buf ^ 1);
        asm volatile("cp.async.commit_group;");
        asm volatile("cp.async.wait_group 1;");
        __syncthreads();

        const int rowlim = bt_total - tile * TILE;   // rows valid in this tile
        // warp handles rows wrow, wrow+4, ..., wrow+124 (32 units), half 'half'
        uint32_t xaddr = (uint32_t)__cvta_generic_to_shared(&xs[buf][wrow * 8]);
        float* obase = out + (size_t)(tile * TILE + wrow) * 128 + half * 64 + lane * 2;
#pragma unroll 4
        for (int j = 0; j < 32; j++) {
            int rit = wrow + j * 4;
            if (rit >= rowlim) break;
            unsigned long long xv0, xv1, xv2, xv3;
            uint32_t a = xaddr + (uint32_t)(j * 4 * 32);  // 4 rows * 32B per j-step
            asm volatile("ld.shared.v2.u64 {%0, %1}, [%2];"
                         : "=l"(xv0), "=l"(xv1) : "r"(a));
            asm volatile("ld.shared.v2.u64 {%0, %1}, [%2];"
                         : "=l"(xv2), "=l"(xv3) : "r"(a + 16));

            unsigned long long acc0 = mul2(w0[0], xv0);
            unsigned long long acc1 = mul2(w1[0], xv0);
            acc0 = fma2(w0[1], xv1, acc0);
            acc1 = fma2(w1[1], xv1, acc1);
            acc0 = fma2(w0[2], xv2, acc0);
            acc1 = fma2(w1[2], xv2, acc1);
            acc0 = fma2(w0[3], xv3, acc0);
            acc1 = fma2(w1[3], xv3, acc1);

            float lo0, hi0, lo1, hi1;
            upk2(lo0, hi0, acc0);
            upk2(lo1, hi1, acc1);
            float2 o;
            o.x = s * tanh_ap(lo0 + hi0);
            o.y = s * tanh_ap(lo1 + hi1);
            __stcs(reinterpret_cast<float2*>(obase + (size_t)j * 4 * 128), o);
        }
        __syncthreads();
        buf ^= 1;
    }
}

extern "C" void kernel_launch(void* const* d_in, const int* in_sizes, int n_in,
                              void* d_out, int out_size)
{
    const float* x   = (const float*)d_in[0];   // [B, T, I] fp32
    const float* w   = (const float*)d_in[1];   // [R, I] fp32
    // d_in[2] = d, unused (contributes exactly 0 in the reference)
    const float* lr  = (const float*)d_in[3];   // [1] fp32
    float* out = (float*)d_out;

    const int bt_total = in_sizes[0] / 8;       // B*T rows

    int ntiles = (bt_total + TILE - 1) / TILE;
    int blocks = 888;                            // 6 blocks/SM x 148 SMs
    if (blocks > ntiles) blocks = ntiles;
    if (blocks < 1) blocks = 1;
    ESN_11390253269642_kernel<<<blocks, 256>>>(x, w, lr, out, bt_total);
}